// round 10
// baseline (speedup 1.0000x reference)
#include <cuda_runtime.h>
#include <math.h>

#define B 128
#define C 1024
#define DIN 1024
#define TWO_D 2048
#define NUM_CLASSES 10
#define ALPHA 1e-3f
#define GAMMA 1e-2f

#define BM 64
#define BN 256
#define BK 32
#define PAD 4
#define KSPLIT 16
#define KSLICE (TWO_D / KSPLIT)   // 128
#define NT (KSLICE / BK)          // 4 tiles

#define SA_STRIDE (BM + PAD)              // 68
#define SB_STRIDE (BN + PAD)              // 260
#define SA_BUF (BK * SA_STRIDE)           // 2176 floats
#define SB_BUF (BK * SB_STRIDE)           // 8320 floats
#define SMEM_FLOATS (2 * SA_BUF + 2 * SB_BUF)
#define SMEM_BYTES (SMEM_FLOATS * 4)      // 83968 B

// Scratch (static device globals; no dynamic allocation)
__device__ float g_pmin[B];
__device__ float g_pmax[B];
__device__ float g_coded[B * TWO_D];
__device__ float g_den[C];
__device__ float g_choice[B][C];   // numerator accumulated via REDG

// ---------------------------------------------------------------------------
// K1: per-batch-row min/max partials of x  +  zero g_choice row b
// ---------------------------------------------------------------------------
__global__ void k_minmax_partial(const float* __restrict__ x) {
    int b = blockIdx.x;
    int t = threadIdx.x;  // 128

    float4 z = make_float4(0.f, 0.f, 0.f, 0.f);
    ((float4*)&g_choice[b][0])[t] = z;
    ((float4*)&g_choice[b][0])[t + 128] = z;

    const float* row = x + b * DIN;
    float mn = 1e30f, mx = -1e30f;
    #pragma unroll
    for (int i = 0; i < 2; i++) {
        float4 v = ((const float4*)row)[t + i * 128];
        mn = fminf(mn, fminf(fminf(v.x, v.y), fminf(v.z, v.w)));
        mx = fmaxf(mx, fmaxf(fmaxf(v.x, v.y), fmaxf(v.z, v.w)));
    }
    #pragma unroll
    for (int o = 16; o > 0; o >>= 1) {
        mn = fminf(mn, __shfl_xor_sync(0xffffffffu, mn, o));
        mx = fmaxf(mx, __shfl_xor_sync(0xffffffffu, mx, o));
    }
    __shared__ float smn[4], smx[4];
    if ((t & 31) == 0) { smn[t >> 5] = mn; smx[t >> 5] = mx; }
    __syncthreads();
    if (t == 0) {
        mn = smn[0]; mx = smx[0];
        #pragma unroll
        for (int w = 1; w < 4; w++) { mn = fminf(mn, smn[w]); mx = fmaxf(mx, smx[w]); }
        g_pmin[b] = mn;
        g_pmax[b] = mx;
    }
}

// ---------------------------------------------------------------------------
// K2: blocks [0,128): den for 8 template rows each (one warp per row)
//     blocks [128,256): final minmax reduce + complement-coded rows
// ---------------------------------------------------------------------------
__global__ void k_prep(const float* __restrict__ x,
                       const float* __restrict__ T,
                       const int* __restrict__ counts) {
    int blk = blockIdx.x;
    int t = threadIdx.x;  // 256
    if (blk < 128) {
        int row = blk * 8 + (t >> 5);
        int lane = t & 31;
        const float4* r = (const float4*)(T + (size_t)row * TWO_D);
        float s = 0.0f;
        #pragma unroll
        for (int i = 0; i < 16; i++) {
            float4 v = r[lane + i * 32];
            s += (v.x + v.y) + (v.z + v.w);
        }
        #pragma unroll
        for (int o = 16; o > 0; o >>= 1)
            s += __shfl_xor_sync(0xffffffffu, s, o);
        if (lane == 0)
            g_den[row] = ALPHA + s + GAMMA * (float)counts[row];
    } else {
        int b = blk - 128;
        __shared__ float smn[4], smx[4];
        float mn = 1e30f, mx = -1e30f;
        if (t < 128) {
            mn = g_pmin[t];
            mx = g_pmax[t];
            #pragma unroll
            for (int o = 16; o > 0; o >>= 1) {
                mn = fminf(mn, __shfl_xor_sync(0xffffffffu, mn, o));
                mx = fmaxf(mx, __shfl_xor_sync(0xffffffffu, mx, o));
            }
            if ((t & 31) == 0) { smn[t >> 5] = mn; smx[t >> 5] = mx; }
        }
        __syncthreads();
        mn = fminf(fminf(smn[0], smn[1]), fminf(smn[2], smn[3]));
        mx = fmaxf(fmaxf(smx[0], smx[1]), fmaxf(smx[2], smx[3]));
        float sc = 1.0f / (mx - mn + 1e-10f);

        const float* xr = x + (size_t)b * DIN;
        float* cr = g_coded + (size_t)b * TWO_D;
        #pragma unroll
        for (int i = 0; i < 4; i++) {
            int k = t + i * 256;
            float xn = (xr[k] - mn) * sc;
            cr[k] = xn;
            cr[DIN + k] = 1.0f - xn;
        }
    }
}

// ---------------------------------------------------------------------------
// K3: min-sum "GEMM". BM=64, BN=256, BK=32, 1024 threads (64x16), TM=TN=4.
// grid = (4, 2, 16) = 128 CTAs = one wave, 8 warps/SMSP.
// Double-buffered dynamic smem, ONE __syncthreads per tile.
// Epilogue: REDG atomicAdd into g_choice.
// ---------------------------------------------------------------------------
__global__ void __launch_bounds__(1024) k_choice(const float* __restrict__ T) {
    extern __shared__ float sm[];
    float* sA = sm;                  // [2][BK][BM+PAD]
    float* sB = sm + 2 * SA_BUF;     // [2][BK][BN+PAD]

    int tid = threadIdx.x;
    int tx = tid & 63;       // n-group -> n0 = tx*4 (BN=256)
    int ty = tid >> 6;       // m-group -> m0 = ty*4 (BM=64)
    int mbase = blockIdx.y * BM;
    int nbase = blockIdx.x * BN;
    int k0 = blockIdx.z * KSLICE;

    bool hasA = tid < 512;
    int ra = tid >> 3;       // A rows 0..63 (tid<512), B rows 0..127
    int kv = tid & 7;        // float4 index within BK

    const float4* pA  = (const float4*)&g_coded[(size_t)(mbase + (hasA ? ra : 0)) * TWO_D + k0 + kv * 4];
    const float4* pB0 = (const float4*)&T[(size_t)(nbase + ra) * TWO_D + k0 + kv * 4];
    const float4* pB1 = (const float4*)&T[(size_t)(nbase + ra + 128) * TWO_D + k0 + kv * 4];

    float acc[4][4];
    #pragma unroll
    for (int i = 0; i < 4; i++)
        #pragma unroll
        for (int j = 0; j < 4; j++) acc[i][j] = 0.0f;

    // prefetch + store tile 0 into buffer 0
    float4 va = make_float4(0.f, 0.f, 0.f, 0.f);
    if (hasA) va = pA[0];
    float4 vb0 = pB0[0], vb1 = pB1[0];
    {
        int kc = kv * 4;
        if (hasA) {
            float* a = sA + kc * SA_STRIDE;
            a[ra] = va.x; a[SA_STRIDE + ra] = va.y;
            a[2 * SA_STRIDE + ra] = va.z; a[3 * SA_STRIDE + ra] = va.w;
        }
        float* bp = sB + kc * SB_STRIDE;
        bp[ra] = vb0.x; bp[SB_STRIDE + ra] = vb0.y;
        bp[2 * SB_STRIDE + ra] = vb0.z; bp[3 * SB_STRIDE + ra] = vb0.w;
        bp[ra + 128] = vb1.x; bp[SB_STRIDE + ra + 128] = vb1.y;
        bp[2 * SB_STRIDE + ra + 128] = vb1.z; bp[3 * SB_STRIDE + ra + 128] = vb1.w;
    }
    __syncthreads();

    int buf = 0;
    for (int tt = 0; tt < NT; tt++) {
        if (tt + 1 < NT) {   // prefetch next tile (overlaps compute below)
            int o = (tt + 1) * (BK / 4);
            if (hasA) va = pA[o];
            vb0 = pB0[o]; vb1 = pB1[o];
        }
        const float* cA = sA + buf * SA_BUF + ty * 4;
        const float* cB = sB + buf * SB_BUF + tx * 4;
        #pragma unroll
        for (int k = 0; k < BK; k++) {
            float4 a = *(const float4*)(cA + k * SA_STRIDE);
            float4 bb = *(const float4*)(cB + k * SB_STRIDE);
            float av[4] = {a.x, a.y, a.z, a.w};
            float bv[4] = {bb.x, bb.y, bb.z, bb.w};
            #pragma unroll
            for (int i = 0; i < 4; i++)
                #pragma unroll
                for (int j = 0; j < 4; j++)
                    acc[i][j] += fminf(av[i], bv[j]);
        }
        if (tt + 1 < NT) {
            int nb = buf ^ 1;
            int kc = kv * 4;
            if (hasA) {
                float* a = sA + nb * SA_BUF + kc * SA_STRIDE;
                a[ra] = va.x; a[SA_STRIDE + ra] = va.y;
                a[2 * SA_STRIDE + ra] = va.z; a[3 * SA_STRIDE + ra] = va.w;
            }
            float* bp = sB + nb * SB_BUF + kc * SB_STRIDE;
            bp[ra] = vb0.x; bp[SB_STRIDE + ra] = vb0.y;
            bp[2 * SB_STRIDE + ra] = vb0.z; bp[3 * SB_STRIDE + ra] = vb0.w;
            bp[ra + 128] = vb1.x; bp[SB_STRIDE + ra + 128] = vb1.y;
            bp[2 * SB_STRIDE + ra + 128] = vb1.z; bp[3 * SB_STRIDE + ra + 128] = vb1.w;
            __syncthreads();
            buf = nb;
        }
    }

    // fire-and-forget reduction into g_choice (REDG)
    int b0 = mbase + ty * 4;
    int c0 = nbase + tx * 4;
    #pragma unroll
    for (int i = 0; i < 4; i++)
        #pragma unroll
        for (int j = 0; j < 4; j++)
            atomicAdd(&g_choice[b0 + i][c0 + j], acc[i][j]);
}

// ---------------------------------------------------------------------------
// K4: per batch row, 256 threads, 4 categories/thread (float4/int4 loads):
// divide by den, masked argmax (first-index tie), per-label sums via
// per-warp smem rows, one-hot output. committed is int32.
// ---------------------------------------------------------------------------
__global__ void __launch_bounds__(256) k_final(const int* __restrict__ committed,
                                               const int* __restrict__ labels,
                                               float* __restrict__ out) {
    int b = blockIdx.x;
    int t = threadIdx.x;        // 0..255, cats c = 4t..4t+3
    int lane = t & 31;
    int wid = t >> 3 >> 2;      // t >> 5
    __shared__ float sbins[8][NUM_CLASSES];
    __shared__ float bins[NUM_CLASSES];
    __shared__ float wval[8];
    __shared__ int widx[8];

    if (lane < NUM_CLASSES) sbins[wid][lane] = 0.0f;
    __syncthreads();

    float4 ch = ((const float4*)&g_choice[b][0])[t];
    float4 dn = ((const float4*)g_den)[t];
    int4 cm = ((const int4*)committed)[t];
    int4 lb = ((const int4*)labels)[t];

    float v[4] = {ch.x / dn.x, ch.y / dn.y, ch.z / dn.z, ch.w / dn.w};
    int cmv[4] = {cm.x, cm.y, cm.z, cm.w};
    int lbv[4] = {lb.x, lb.y, lb.z, lb.w};

    int c0 = t * 4;
    float best = -INFINITY;
    int bidx = c0;
    #pragma unroll
    for (int j = 0; j < 4; j++) {
        if (cmv[j]) {
            atomicAdd(&sbins[wid][lbv[j]], v[j]);
            if (v[j] > best) { best = v[j]; bidx = c0 + j; }  // ascending -> first idx
        }
    }

    // warp argmax, first-index on tie
    #pragma unroll
    for (int o = 16; o > 0; o >>= 1) {
        float ov = __shfl_xor_sync(0xffffffffu, best, o);
        int oi = __shfl_xor_sync(0xffffffffu, bidx, o);
        if (ov > best || (ov == best && oi < bidx)) { best = ov; bidx = oi; }
    }
    if (lane == 0) { wval[wid] = best; widx[wid] = bidx; }
    __syncthreads();

    if (wid == 0) {
        best = (lane < 8) ? wval[lane] : -INFINITY;
        bidx = (lane < 8) ? widx[lane] : (C + 1);
        #pragma unroll
        for (int o = 16; o > 0; o >>= 1) {
            float ov = __shfl_xor_sync(0xffffffffu, best, o);
            int oi = __shfl_xor_sync(0xffffffffu, bidx, o);
            if (ov > best || (ov == best && oi < bidx)) { best = ov; bidx = oi; }
        }
        if (lane == 0) widx[0] = bidx;
    } else if (wid == 1 && lane < NUM_CLASSES) {
        float s = 0.0f;
        #pragma unroll
        for (int w = 0; w < 8; w++) s += sbins[w][lane];
        bins[lane] = s;
    }
    __syncthreads();

    if (t < NUM_CLASSES) {
        int pl = labels[widx[0]];
        out[b * NUM_CLASSES + t] = (t == pl) ? bins[t] : 0.0f;
    }
}

// ---------------------------------------------------------------------------
extern "C" void kernel_launch(void* const* d_in, const int* in_sizes, int n_in,
                              void* d_out, int out_size) {
    const float* x = (const float*)d_in[0];
    const float* T = (const float*)d_in[1];
    const int* committed = (const int*)d_in[2];
    const int* labels = (const int*)d_in[3];
    const int* counts = (const int*)d_in[4];
    float* out = (float*)d_out;

    cudaFuncSetAttribute(k_choice, cudaFuncAttributeMaxDynamicSharedMemorySize,
                         SMEM_BYTES);

    k_minmax_partial<<<B, 128>>>(x);
    k_prep<<<256, 256>>>(x, T, counts);
    dim3 g3(C / BN, B / BM, KSPLIT);
    k_choice<<<g3, 1024, SMEM_BYTES>>>(T);
    k_final<<<B, 256>>>(committed, labels, out);
}

// round 11
// speedup vs baseline: 1.0517x; 1.0517x over previous
#include <cuda_runtime.h>
#include <math.h>

#define B 128
#define C 1024
#define DIN 1024
#define TWO_D 2048
#define NUM_CLASSES 10
#define ALPHA 1e-3f
#define GAMMA 1e-2f

#define BM 64
#define BN 256
#define BK 32
#define PAD 4
#define KSPLIT 16
#define KSLICE (TWO_D / KSPLIT)   // 128  (<= DIN and aligned: slice is in one half)
#define NT (KSLICE / BK)          // 4 tiles

#define SA_STRIDE (BM + PAD)              // 68
#define SB_STRIDE (BN + PAD)              // 260
#define SA_BUF (BK * SA_STRIDE)           // 2176 floats
#define SB_BUF (BK * SB_STRIDE)           // 8320 floats
#define SMEM_FLOATS (2 * SA_BUF + 2 * SB_BUF)
#define SMEM_BYTES (SMEM_FLOATS * 4)      // 83968 B

// Scratch (static device globals; no dynamic allocation)
__device__ float g_pmin[B];
__device__ float g_pmax[B];
__device__ float g_den[C];
__device__ float g_choice[B][C];   // numerator accumulated via REDG

// ---------------------------------------------------------------------------
// K1: blocks [0,128): den for 8 template rows each (one warp per row)
//     blocks [128,256): b = blk-128: zero g_choice row b + minmax partial of
//     x row b -> g_pmin[b], g_pmax[b]
// ---------------------------------------------------------------------------
__global__ void k_prep(const float* __restrict__ x,
                       const float* __restrict__ T,
                       const int* __restrict__ counts) {
    int blk = blockIdx.x;
    int t = threadIdx.x;  // 256
    if (blk < 128) {
        int row = blk * 8 + (t >> 5);
        int lane = t & 31;
        const float4* r = (const float4*)(T + (size_t)row * TWO_D);
        float s = 0.0f;
        #pragma unroll
        for (int i = 0; i < 16; i++) {
            float4 v = r[lane + i * 32];
            s += (v.x + v.y) + (v.z + v.w);
        }
        #pragma unroll
        for (int o = 16; o > 0; o >>= 1)
            s += __shfl_xor_sync(0xffffffffu, s, o);
        if (lane == 0)
            g_den[row] = ALPHA + s + GAMMA * (float)counts[row];
    } else {
        int b = blk - 128;
        // zero this row of g_choice (1 float4 per thread)
        ((float4*)&g_choice[b][0])[t] = make_float4(0.f, 0.f, 0.f, 0.f);

        // minmax of x row b (1 float4 per thread)
        float4 v = ((const float4*)(x + (size_t)b * DIN))[t];
        float mn = fminf(fminf(v.x, v.y), fminf(v.z, v.w));
        float mx = fmaxf(fmaxf(v.x, v.y), fmaxf(v.z, v.w));
        #pragma unroll
        for (int o = 16; o > 0; o >>= 1) {
            mn = fminf(mn, __shfl_xor_sync(0xffffffffu, mn, o));
            mx = fmaxf(mx, __shfl_xor_sync(0xffffffffu, mx, o));
        }
        __shared__ float smn[8], smx[8];
        if ((t & 31) == 0) { smn[t >> 5] = mn; smx[t >> 5] = mx; }
        __syncthreads();
        if (t == 0) {
            #pragma unroll
            for (int w = 1; w < 8; w++) { mn = fminf(mn, smn[w]); mx = fmaxf(mx, smx[w]); }
            g_pmin[b] = mn;
            g_pmax[b] = mx;
        }
    }
}

// ---------------------------------------------------------------------------
// K2: min-sum "GEMM". BM=64, BN=256, BK=32, 1024 threads (64x16), TM=TN=4.
// grid = (4, 2, 16) = 128 CTAs = one wave, 8 warps/SMSP.
// A is built on the fly from x (normalize + optional complement) — no g_coded.
// Inline 128->1 minmax reduce at kernel start. Double-buffered dynamic smem.
// Epilogue: REDG atomicAdd into g_choice.
// ---------------------------------------------------------------------------
__global__ void __launch_bounds__(1024) k_choice(const float* __restrict__ x,
                                                 const float* __restrict__ T) {
    extern __shared__ float sm[];
    float* sA = sm;                  // [2][BK][BM+PAD]
    float* sB = sm + 2 * SA_BUF;     // [2][BK][BN+PAD]

    int tid = threadIdx.x;
    int tx = tid & 63;       // n-group -> n0 = tx*4 (BN=256)
    int ty = tid >> 6;       // m-group -> m0 = ty*4 (BM=64)
    int mbase = blockIdx.y * BM;
    int nbase = blockIdx.x * BN;
    int k0 = blockIdx.z * KSLICE;
    bool comp = (k0 >= DIN);             // slice lies in the complement half
    int xcol = comp ? (k0 - DIN) : k0;   // source column in x

    // ---- inline global minmax reduce (128 partials -> mn, sc) ----
    __shared__ float smn[4], smx[4];
    if (tid < 128) {
        float mn = g_pmin[tid];
        float mx = g_pmax[tid];
        #pragma unroll
        for (int o = 16; o > 0; o >>= 1) {
            mn = fminf(mn, __shfl_xor_sync(0xffffffffu, mn, o));
            mx = fmaxf(mx, __shfl_xor_sync(0xffffffffu, mx, o));
        }
        if ((tid & 31) == 0) { smn[tid >> 5] = mn; smx[tid >> 5] = mx; }
    }
    __syncthreads();
    float mnv = fminf(fminf(smn[0], smn[1]), fminf(smn[2], smn[3]));
    float mxv = fmaxf(fmaxf(smx[0], smx[1]), fmaxf(smx[2], smx[3]));
    float sc = 1.0f / (mxv - mnv + 1e-10f);

    bool hasA = tid < 512;
    int ra = tid >> 3;       // A rows 0..63 (tid<512), B rows 0..127
    int kv = tid & 7;        // float4 index within BK

    const float4* pA  = (const float4*)&x[(size_t)(mbase + (hasA ? ra : 0)) * DIN + xcol + kv * 4];
    const float4* pB0 = (const float4*)&T[(size_t)(nbase + ra) * TWO_D + k0 + kv * 4];
    const float4* pB1 = (const float4*)&T[(size_t)(nbase + ra + 128) * TWO_D + k0 + kv * 4];

    float acc[4][4];
    #pragma unroll
    for (int i = 0; i < 4; i++)
        #pragma unroll
        for (int j = 0; j < 4; j++) acc[i][j] = 0.0f;

    // normalize + complement transform for an A float4
    #define XFORM(v) do { \
        v.x = (v.x - mnv) * sc; v.y = (v.y - mnv) * sc; \
        v.z = (v.z - mnv) * sc; v.w = (v.w - mnv) * sc; \
        if (comp) { v.x = 1.0f - v.x; v.y = 1.0f - v.y; \
                    v.z = 1.0f - v.z; v.w = 1.0f - v.w; } \
    } while (0)

    // prefetch + store tile 0 into buffer 0
    float4 va = make_float4(0.f, 0.f, 0.f, 0.f);
    if (hasA) va = pA[0];
    float4 vb0 = pB0[0], vb1 = pB1[0];
    {
        int kc = kv * 4;
        if (hasA) {
            XFORM(va);
            float* a = sA + kc * SA_STRIDE;
            a[ra] = va.x; a[SA_STRIDE + ra] = va.y;
            a[2 * SA_STRIDE + ra] = va.z; a[3 * SA_STRIDE + ra] = va.w;
        }
        float* bp = sB + kc * SB_STRIDE;
        bp[ra] = vb0.x; bp[SB_STRIDE + ra] = vb0.y;
        bp[2 * SB_STRIDE + ra] = vb0.z; bp[3 * SB_STRIDE + ra] = vb0.w;
        bp[ra + 128] = vb1.x; bp[SB_STRIDE + ra + 128] = vb1.y;
        bp[2 * SB_STRIDE + ra + 128] = vb1.z; bp[3 * SB_STRIDE + ra + 128] = vb1.w;
    }
    __syncthreads();

    int buf = 0;
    for (int tt = 0; tt < NT; tt++) {
        if (tt + 1 < NT) {   // prefetch next tile (overlaps compute below)
            int o = (tt + 1) * (BK / 4);
            if (hasA) va = pA[o];
            vb0 = pB0[o]; vb1 = pB1[o];
        }
        const float* cA = sA + buf * SA_BUF + ty * 4;
        const float* cB = sB + buf * SB_BUF + tx * 4;
        #pragma unroll
        for (int k = 0; k < BK; k++) {
            float4 a = *(const float4*)(cA + k * SA_STRIDE);
            float4 bb = *(const float4*)(cB + k * SB_STRIDE);
            float av[4] = {a.x, a.y, a.z, a.w};
            float bv[4] = {bb.x, bb.y, bb.z, bb.w};
            #pragma unroll
            for (int i = 0; i < 4; i++)
                #pragma unroll
                for (int j = 0; j < 4; j++)
                    acc[i][j] += fminf(av[i], bv[j]);
        }
        if (tt + 1 < NT) {
            int nb = buf ^ 1;
            int kc = kv * 4;
            if (hasA) {
                XFORM(va);
                float* a = sA + nb * SA_BUF + kc * SA_STRIDE;
                a[ra] = va.x; a[SA_STRIDE + ra] = va.y;
                a[2 * SA_STRIDE + ra] = va.z; a[3 * SA_STRIDE + ra] = va.w;
            }
            float* bp = sB + nb * SB_BUF + kc * SB_STRIDE;
            bp[ra] = vb0.x; bp[SB_STRIDE + ra] = vb0.y;
            bp[2 * SB_STRIDE + ra] = vb0.z; bp[3 * SB_STRIDE + ra] = vb0.w;
            bp[ra + 128] = vb1.x; bp[SB_STRIDE + ra + 128] = vb1.y;
            bp[2 * SB_STRIDE + ra + 128] = vb1.z; bp[3 * SB_STRIDE + ra + 128] = vb1.w;
            __syncthreads();
            buf = nb;
        }
    }
    #undef XFORM

    // fire-and-forget reduction into g_choice (REDG)
    int b0 = mbase + ty * 4;
    int c0 = nbase + tx * 4;
    #pragma unroll
    for (int i = 0; i < 4; i++)
        #pragma unroll
        for (int j = 0; j < 4; j++)
            atomicAdd(&g_choice[b0 + i][c0 + j], acc[i][j]);
}

// ---------------------------------------------------------------------------
// K3: per batch row, 256 threads, 4 categories/thread (float4/int4 loads):
// divide by den, masked argmax (first-index tie), per-label sums via
// per-warp smem rows, one-hot output. committed is int32.
// ---------------------------------------------------------------------------
__global__ void __launch_bounds__(256) k_final(const int* __restrict__ committed,
                                               const int* __restrict__ labels,
                                               float* __restrict__ out) {
    int b = blockIdx.x;
    int t = threadIdx.x;        // 0..255, cats c = 4t..4t+3
    int lane = t & 31;
    int wid = t >> 5;
    __shared__ float sbins[8][NUM_CLASSES];
    __shared__ float bins[NUM_CLASSES];
    __shared__ float wval[8];
    __shared__ int widx[8];

    if (lane < NUM_CLASSES) sbins[wid][lane] = 0.0f;
    __syncthreads();

    float4 ch = ((const float4*)&g_choice[b][0])[t];
    float4 dn = ((const float4*)g_den)[t];
    int4 cm = ((const int4*)committed)[t];
    int4 lb = ((const int4*)labels)[t];

    float v[4] = {ch.x / dn.x, ch.y / dn.y, ch.z / dn.z, ch.w / dn.w};
    int cmv[4] = {cm.x, cm.y, cm.z, cm.w};
    int lbv[4] = {lb.x, lb.y, lb.z, lb.w};

    int c0 = t * 4;
    float best = -INFINITY;
    int bidx = c0;
    #pragma unroll
    for (int j = 0; j < 4; j++) {
        if (cmv[j]) {
            atomicAdd(&sbins[wid][lbv[j]], v[j]);
            if (v[j] > best) { best = v[j]; bidx = c0 + j; }  // ascending -> first idx
        }
    }

    // warp argmax, first-index on tie
    #pragma unroll
    for (int o = 16; o > 0; o >>= 1) {
        float ov = __shfl_xor_sync(0xffffffffu, best, o);
        int oi = __shfl_xor_sync(0xffffffffu, bidx, o);
        if (ov > best || (ov == best && oi < bidx)) { best = ov; bidx = oi; }
    }
    if (lane == 0) { wval[wid] = best; widx[wid] = bidx; }
    __syncthreads();

    if (wid == 0) {
        best = (lane < 8) ? wval[lane] : -INFINITY;
        bidx = (lane < 8) ? widx[lane] : (C + 1);
        #pragma unroll
        for (int o = 16; o > 0; o >>= 1) {
            float ov = __shfl_xor_sync(0xffffffffu, best, o);
            int oi = __shfl_xor_sync(0xffffffffu, bidx, o);
            if (ov > best || (ov == best && oi < bidx)) { best = ov; bidx = oi; }
        }
        if (lane == 0) widx[0] = bidx;
    } else if (wid == 1 && lane < NUM_CLASSES) {
        float s = 0.0f;
        #pragma unroll
        for (int w = 0; w < 8; w++) s += sbins[w][lane];
        bins[lane] = s;
    }
    __syncthreads();

    if (t < NUM_CLASSES) {
        int pl = labels[widx[0]];
        out[b * NUM_CLASSES + t] = (t == pl) ? bins[t] : 0.0f;
    }
}

// ---------------------------------------------------------------------------
extern "C" void kernel_launch(void* const* d_in, const int* in_sizes, int n_in,
                              void* d_out, int out_size) {
    const float* x = (const float*)d_in[0];
    const float* T = (const float*)d_in[1];
    const int* committed = (const int*)d_in[2];
    const int* labels = (const int*)d_in[3];
    const int* counts = (const int*)d_in[4];
    float* out = (float*)d_out;

    cudaFuncSetAttribute(k_choice, cudaFuncAttributeMaxDynamicSharedMemorySize,
                         SMEM_BYTES);

    k_prep<<<256, 256>>>(x, T, counts);
    dim3 g3(C / BN, B / BM, KSPLIT);
    k_choice<<<g3, 1024, SMEM_BYTES>>>(x, T);
    k_final<<<B, 256>>>(committed, labels, out);
}

// round 12
// speedup vs baseline: 1.0585x; 1.0065x over previous
#include <cuda_runtime.h>
#include <math.h>

#define B 128
#define C 1024
#define DIN 1024
#define TWO_D 2048
#define NUM_CLASSES 10
#define ALPHA 1e-3f
#define GAMMA 1e-2f

#define BM 64
#define BN 256
#define BK 32
#define PAD 4
#define KSPLIT 16
#define KSLICE (TWO_D / KSPLIT)   // 128  (aligned: each slice is in one half)
#define NT (KSLICE / BK)          // 4 tiles

#define SA_STRIDE (BM + PAD)              // 68
#define SB_STRIDE (BN + PAD)              // 260
#define SA_BUF (BK * SA_STRIDE)           // 2176 floats
#define SB_BUF (BK * SB_STRIDE)           // 8320 floats
#define SMEM_FLOATS (2 * SA_BUF + 2 * SB_BUF)
#define SMEM_BYTES (SMEM_FLOATS * 4)      // 83968 B

// Scratch (static device globals; no dynamic allocation)
__device__ float g_pmin[B];
__device__ float g_pmax[B];
__device__ float g_sum[C];         // rowsum(T) accumulated via REDG in k_choice
__device__ float g_choice[B][C];   // numerator accumulated via REDG

// ---------------------------------------------------------------------------
// K1 (128 CTAs x 256): row b: zero g_choice row + minmax partial of x row.
// CTA 0 additionally zeroes g_sum.
// ---------------------------------------------------------------------------
__global__ void k_prep(const float* __restrict__ x) {
    int b = blockIdx.x;
    int t = threadIdx.x;  // 256

    ((float4*)&g_choice[b][0])[t] = make_float4(0.f, 0.f, 0.f, 0.f);
    if (b == 0)
        ((float4*)g_sum)[t] = make_float4(0.f, 0.f, 0.f, 0.f);

    float4 v = ((const float4*)(x + (size_t)b * DIN))[t];
    float mn = fminf(fminf(v.x, v.y), fminf(v.z, v.w));
    float mx = fmaxf(fmaxf(v.x, v.y), fmaxf(v.z, v.w));
    #pragma unroll
    for (int o = 16; o > 0; o >>= 1) {
        mn = fminf(mn, __shfl_xor_sync(0xffffffffu, mn, o));
        mx = fmaxf(mx, __shfl_xor_sync(0xffffffffu, mx, o));
    }
    __shared__ float smn[8], smx[8];
    if ((t & 31) == 0) { smn[t >> 5] = mn; smx[t >> 5] = mx; }
    __syncthreads();
    if (t == 0) {
        #pragma unroll
        for (int w = 1; w < 8; w++) { mn = fminf(mn, smn[w]); mx = fmaxf(mx, smx[w]); }
        g_pmin[b] = mn;
        g_pmax[b] = mx;
    }
}

// ---------------------------------------------------------------------------
// K2: min-sum "GEMM". BM=64, BN=256, BK=32, 1024 threads, TM=TN=4.
// grid = (4, 2, 16) = 128 CTAs = one wave, 8 warps/SMSP.
// A built on the fly from x (normalize + optional complement).
// Inline 128->1 minmax reduce at kernel start. Double-buffered dynamic smem.
// Side-product: rowsum(T) partials REDG'd into g_sum (blockIdx.y==0 only,
// since both m-blocks load the identical B tile).
// Epilogue: REDG atomicAdd into g_choice.
// ---------------------------------------------------------------------------
__global__ void __launch_bounds__(1024) k_choice(const float* __restrict__ x,
                                                 const float* __restrict__ T) {
    extern __shared__ float sm[];
    float* sA = sm;                  // [2][BK][BM+PAD]
    float* sB = sm + 2 * SA_BUF;     // [2][BK][BN+PAD]

    int tid = threadIdx.x;
    int tx = tid & 63;       // n-group -> n0 = tx*4 (BN=256)
    int ty = tid >> 6;       // m-group -> m0 = ty*4 (BM=64)
    int mbase = blockIdx.y * BM;
    int nbase = blockIdx.x * BN;
    int k0 = blockIdx.z * KSLICE;
    bool comp = (k0 >= DIN);             // slice lies in the complement half
    int xcol = comp ? (k0 - DIN) : k0;   // source column in x
    bool sumDuty = (blockIdx.y == 0);    // avoid double-counting rowsum(T)

    // ---- inline global minmax reduce (128 partials -> mn, sc) ----
    __shared__ float smn[4], smx[4];
    if (tid < 128) {
        float mn = g_pmin[tid];
        float mx = g_pmax[tid];
        #pragma unroll
        for (int o = 16; o > 0; o >>= 1) {
            mn = fminf(mn, __shfl_xor_sync(0xffffffffu, mn, o));
            mx = fmaxf(mx, __shfl_xor_sync(0xffffffffu, mx, o));
        }
        if ((tid & 31) == 0) { smn[tid >> 5] = mn; smx[tid >> 5] = mx; }
    }
    __syncthreads();
    float mnv = fminf(fminf(smn[0], smn[1]), fminf(smn[2], smn[3]));
    float mxv = fmaxf(fmaxf(smx[0], smx[1]), fmaxf(smx[2], smx[3]));
    float sc = 1.0f / (mxv - mnv + 1e-10f);

    bool hasA = tid < 512;
    int ra = tid >> 3;       // A rows 0..63 (tid<512), B rows 0..127
    int kv = tid & 7;        // float4 index within BK

    const float4* pA  = (const float4*)&x[(size_t)(mbase + (hasA ? ra : 0)) * DIN + xcol + kv * 4];
    const float4* pB0 = (const float4*)&T[(size_t)(nbase + ra) * TWO_D + k0 + kv * 4];
    const float4* pB1 = (const float4*)&T[(size_t)(nbase + ra + 128) * TWO_D + k0 + kv * 4];

    float acc[4][4];
    #pragma unroll
    for (int i = 0; i < 4; i++)
        #pragma unroll
        for (int j = 0; j < 4; j++) acc[i][j] = 0.0f;

    float tsum0 = 0.0f, tsum1 = 0.0f;   // rowsum(T) partials for rows ra, ra+128

    #define XFORM(v) do { \
        v.x = (v.x - mnv) * sc; v.y = (v.y - mnv) * sc; \
        v.z = (v.z - mnv) * sc; v.w = (v.w - mnv) * sc; \
        if (comp) { v.x = 1.0f - v.x; v.y = 1.0f - v.y; \
                    v.z = 1.0f - v.z; v.w = 1.0f - v.w; } \
    } while (0)

    // prefetch + store tile 0 into buffer 0
    float4 va = make_float4(0.f, 0.f, 0.f, 0.f);
    if (hasA) va = pA[0];
    float4 vb0 = pB0[0], vb1 = pB1[0];
    tsum0 += (vb0.x + vb0.y) + (vb0.z + vb0.w);
    tsum1 += (vb1.x + vb1.y) + (vb1.z + vb1.w);
    {
        int kc = kv * 4;
        if (hasA) {
            XFORM(va);
            float* a = sA + kc * SA_STRIDE;
            a[ra] = va.x; a[SA_STRIDE + ra] = va.y;
            a[2 * SA_STRIDE + ra] = va.z; a[3 * SA_STRIDE + ra] = va.w;
        }
        float* bp = sB + kc * SB_STRIDE;
        bp[ra] = vb0.x; bp[SB_STRIDE + ra] = vb0.y;
        bp[2 * SB_STRIDE + ra] = vb0.z; bp[3 * SB_STRIDE + ra] = vb0.w;
        bp[ra + 128] = vb1.x; bp[SB_STRIDE + ra + 128] = vb1.y;
        bp[2 * SB_STRIDE + ra + 128] = vb1.z; bp[3 * SB_STRIDE + ra + 128] = vb1.w;
    }
    __syncthreads();

    int buf = 0;
    for (int tt = 0; tt < NT; tt++) {
        if (tt + 1 < NT) {   // prefetch next tile (overlaps compute below)
            int o = (tt + 1) * (BK / 4);
            if (hasA) va = pA[o];
            vb0 = pB0[o]; vb1 = pB1[o];
            tsum0 += (vb0.x + vb0.y) + (vb0.z + vb0.w);
            tsum1 += (vb1.x + vb1.y) + (vb1.z + vb1.w);
        }
        const float* cA = sA + buf * SA_BUF + ty * 4;
        const float* cB = sB + buf * SB_BUF + tx * 4;
        #pragma unroll
        for (int k = 0; k < BK; k++) {
            float4 a = *(const float4*)(cA + k * SA_STRIDE);
            float4 bb = *(const float4*)(cB + k * SB_STRIDE);
            float av[4] = {a.x, a.y, a.z, a.w};
            float bv[4] = {bb.x, bb.y, bb.z, bb.w};
            #pragma unroll
            for (int i = 0; i < 4; i++)
                #pragma unroll
                for (int j = 0; j < 4; j++)
                    acc[i][j] += fminf(av[i], bv[j]);
        }
        if (tt + 1 < NT) {
            int nb = buf ^ 1;
            int kc = kv * 4;
            if (hasA) {
                XFORM(va);
                float* a = sA + nb * SA_BUF + kc * SA_STRIDE;
                a[ra] = va.x; a[SA_STRIDE + ra] = va.y;
                a[2 * SA_STRIDE + ra] = va.z; a[3 * SA_STRIDE + ra] = va.w;
            }
            float* bp = sB + nb * SB_BUF + kc * SB_STRIDE;
            bp[ra] = vb0.x; bp[SB_STRIDE + ra] = vb0.y;
            bp[2 * SB_STRIDE + ra] = vb0.z; bp[3 * SB_STRIDE + ra] = vb0.w;
            bp[ra + 128] = vb1.x; bp[SB_STRIDE + ra + 128] = vb1.y;
            bp[2 * SB_STRIDE + ra + 128] = vb1.z; bp[3 * SB_STRIDE + ra + 128] = vb1.w;
            __syncthreads();
            buf = nb;
        }
    }
    #undef XFORM

    // rowsum(T) partials (once per B tile: blockIdx.y == 0 only)
    if (sumDuty) {
        atomicAdd(&g_sum[nbase + ra], tsum0);
        atomicAdd(&g_sum[nbase + ra + 128], tsum1);
    }

    // fire-and-forget reduction into g_choice (REDG)
    int b0 = mbase + ty * 4;
    int c0 = nbase + tx * 4;
    #pragma unroll
    for (int i = 0; i < 4; i++)
        #pragma unroll
        for (int j = 0; j < 4; j++)
            atomicAdd(&g_choice[b0 + i][c0 + j], acc[i][j]);
}

// ---------------------------------------------------------------------------
// K3: per batch row, 256 threads, 4 categories/thread (float4/int4 loads):
// den = alpha + g_sum[c] + gamma*counts[c]; divide, masked argmax
// (first-index tie), per-label sums via per-warp smem rows, one-hot output.
// committed is int32.
// ---------------------------------------------------------------------------
__global__ void __launch_bounds__(256) k_final(const int* __restrict__ committed,
                                               const int* __restrict__ labels,
                                               const int* __restrict__ counts,
                                               float* __restrict__ out) {
    int b = blockIdx.x;
    int t = threadIdx.x;        // 0..255, cats c = 4t..4t+3
    int lane = t & 31;
    int wid = t >> 5;
    __shared__ float sbins[8][NUM_CLASSES];
    __shared__ float bins[NUM_CLASSES];
    __shared__ float wval[8];
    __shared__ int widx[8];

    if (lane < NUM_CLASSES) sbins[wid][lane] = 0.0f;
    __syncthreads();

    float4 ch = ((const float4*)&g_choice[b][0])[t];
    float4 sn = ((const float4*)g_sum)[t];
    int4 cm = ((const int4*)committed)[t];
    int4 lb = ((const int4*)labels)[t];
    int4 cn = ((const int4*)counts)[t];

    float den[4] = {ALPHA + sn.x + GAMMA * (float)cn.x,
                    ALPHA + sn.y + GAMMA * (float)cn.y,
                    ALPHA + sn.z + GAMMA * (float)cn.z,
                    ALPHA + sn.w + GAMMA * (float)cn.w};
    float v[4] = {ch.x / den[0], ch.y / den[1], ch.z / den[2], ch.w / den[3]};
    int cmv[4] = {cm.x, cm.y, cm.z, cm.w};
    int lbv[4] = {lb.x, lb.y, lb.z, lb.w};

    int c0 = t * 4;
    float best = -INFINITY;
    int bidx = c0;
    #pragma unroll
    for (int j = 0; j < 4; j++) {
        if (cmv[j]) {
            atomicAdd(&sbins[wid][lbv[j]], v[j]);
            if (v[j] > best) { best = v[j]; bidx = c0 + j; }  // ascending -> first idx
        }
    }

    // warp argmax, first-index on tie
    #pragma unroll
    for (int o = 16; o > 0; o >>= 1) {
        float ov = __shfl_xor_sync(0xffffffffu, best, o);
        int oi = __shfl_xor_sync(0xffffffffu, bidx, o);
        if (ov > best || (ov == best && oi < bidx)) { best = ov; bidx = oi; }
    }
    if (lane == 0) { wval[wid] = best; widx[wid] = bidx; }
    __syncthreads();

    if (wid == 0) {
        best = (lane < 8) ? wval[lane] : -INFINITY;
        bidx = (lane < 8) ? widx[lane] : (C + 1);
        #pragma unroll
        for (int o = 16; o > 0; o >>= 1) {
            float ov = __shfl_xor_sync(0xffffffffu, best, o);
            int oi = __shfl_xor_sync(0xffffffffu, bidx, o);
            if (ov > best || (ov == best && oi < bidx)) { best = ov; bidx = oi; }
        }
        if (lane == 0) widx[0] = bidx;
    } else if (wid == 1 && lane < NUM_CLASSES) {
        float s = 0.0f;
        #pragma unroll
        for (int w = 0; w < 8; w++) s += sbins[w][lane];
        bins[lane] = s;
    }
    __syncthreads();

    if (t < NUM_CLASSES) {
        int pl = labels[widx[0]];
        out[b * NUM_CLASSES + t] = (t == pl) ? bins[t] : 0.0f;
    }
}

// ---------------------------------------------------------------------------
extern "C" void kernel_launch(void* const* d_in, const int* in_sizes, int n_in,
                              void* d_out, int out_size) {
    const float* x = (const float*)d_in[0];
    const float* T = (const float*)d_in[1];
    const int* committed = (const int*)d_in[2];
    const int* labels = (const int*)d_in[3];
    const int* counts = (const int*)d_in[4];
    float* out = (float*)d_out;

    cudaFuncSetAttribute(k_choice, cudaFuncAttributeMaxDynamicSharedMemorySize,
                         SMEM_BYTES);

    k_prep<<<B, 256>>>(x);
    dim3 g3(C / BN, B / BM, KSPLIT);
    k_choice<<<g3, 1024, SMEM_BYTES>>>(x, T);
    k_final<<<B, 256>>>(committed, labels, counts, out);
}